// round 6
// baseline (speedup 1.0000x reference)
#include <cuda_runtime.h>
#include <cuda_bf16.h>
#include <cstdint>

// AttentionConv: q,k,v = 1x1 convs; per-channel softmax over 7x7 window of
// q*(k+bias); out = sum attn*v.  B=4, C=Cout=64, H=W=64, K=7, PAD=3.
//
// R5: tcgen05 is feature-gated off in this toolchain (ptxas targets sm_103,
//     no 'a').  qkv GEMM moved to warp-level mma.sync bf16 (HMMA, baseline
//     PTX) with the 3-term Markidis split (K=192): Whi.xhi + Whi.xlo +
//     Wlo.xhi; missing Wlo.xlo ~ 2^-16 rel.  Physical smem stores only
//     [Whi|Wlo] and [xhi;xlo]; segment 3 re-addresses hi rows.  A=W via
//     ldmatrix.x4 (row-major), B=x via ldmatrix.x2.trans (natural [ch][px]
//     layout, no transpose).  Epilogue writes [oc][px] directly (float2).
//     attn kernel unchanged from R3.

#define LOG2E 1.4426950408889634f

__device__ float g_q[4 * 64 * 64 * 64];
__device__ float g_k[4 * 64 * 64 * 64];
__device__ float g_v[4 * 64 * 64 * 64];

__device__ __forceinline__ uint32_t smem_to_u32(const void* p) {
    uint32_t a;
    asm("{ .reg .u64 t; cvta.to.shared.u64 t, %1; cvt.u32.u64 %0, t; }"
        : "=r"(a) : "l"(p));
    return a;
}

// ---------------------------------------------------------------------------
// Kernel 1: qkv via mma.sync (bf16, 3-term split).
// grid = (256 px-tiles, 3 mats), 128 threads.
// Block: D[64 oc, 64 px] = W'[64, 192] . x'[192, 64].
// smem As[oc][k] k<64=Whi k>=64=Wlo, stride 136 bf16 (272B = 16*17, odd ->
// conflict-free ldmatrix).  Bs[k][px] k<64=xhi k>=64=xlo, stride 72 (144B).
// 12 K-steps: s<4: Whi x xhi; 4-7: Whi x xlo; 8-11: Wlo x xhi.
// Warp w owns px [16w, 16w+16): 4 m-tiles x 2 n-tiles, 96 mma total.
// ---------------------------------------------------------------------------
#define RA 136
#define RB 72

__global__ __launch_bounds__(128) void qkv_mma_kernel(
    const float* __restrict__ x, const float* __restrict__ y,
    const float* __restrict__ Wq, const float* __restrict__ Wk,
    const float* __restrict__ Wv) {
    __shared__ __align__(16) __nv_bfloat16 As[64 * RA];    // 17408 B
    __shared__ __align__(16) __nv_bfloat16 Bs[128 * RB];   // 18432 B

    const int mat = blockIdx.y;
    const float* Wsrc = (mat == 0) ? Wq : ((mat == 1) ? Wk : Wv);
    const float* src  = (mat == 2) ? y : x;
    float* dst = (mat == 0) ? g_q : ((mat == 1) ? g_k : g_v);

    const int tid = threadIdx.x;
    const int pix0 = blockIdx.x << 6;      // 64 px, same batch plane
    const int b = pix0 >> 12;
    const int hw0 = pix0 & 4095;
    const float* srcp = src + ((long)(b << 6) << 12) + hw0;

    // ---- W split: 2048 float2 reads, hi->k<64, lo->k>=64 ----
    const float2* W2 = (const float2*)Wsrc;
    for (int i = tid; i < 2048; i += 128) {
        int o = i >> 5, cp = i & 31;       // channel pair 2cp, 2cp+1
        float2 w = W2[i];
        __nv_bfloat16 h0 = __float2bfloat16(w.x);
        __nv_bfloat16 h1 = __float2bfloat16(w.y);
        uint32_t hiw = (uint32_t)__bfloat16_as_ushort(h0) |
                       ((uint32_t)__bfloat16_as_ushort(h1) << 16);
        __nv_bfloat16 l0 = __float2bfloat16(w.x - __bfloat162float(h0));
        __nv_bfloat16 l1 = __float2bfloat16(w.y - __bfloat162float(h1));
        uint32_t low = (uint32_t)__bfloat16_as_ushort(l0) |
                       ((uint32_t)__bfloat16_as_ushort(l1) << 16);
        *(uint32_t*)&As[o * RA + 2 * cp]      = hiw;
        *(uint32_t*)&As[o * RA + 64 + 2 * cp] = low;
    }
    // ---- x split: [ch][px] natural rows; hi->row ch, lo->row 64+ch ----
    for (int i = tid; i < 2048; i += 128) {
        int ch = i >> 5, pp = i & 31;      // px pair 2pp, 2pp+1
        float2 v = *(const float2*)(srcp + (ch << 12) + 2 * pp);
        __nv_bfloat16 h0 = __float2bfloat16(v.x);
        __nv_bfloat16 h1 = __float2bfloat16(v.y);
        uint32_t hiw = (uint32_t)__bfloat16_as_ushort(h0) |
                       ((uint32_t)__bfloat16_as_ushort(h1) << 16);
        __nv_bfloat16 l0 = __float2bfloat16(v.x - __bfloat162float(h0));
        __nv_bfloat16 l1 = __float2bfloat16(v.y - __bfloat162float(h1));
        uint32_t low = (uint32_t)__bfloat16_as_ushort(l0) |
                       ((uint32_t)__bfloat16_as_ushort(l1) << 16);
        *(uint32_t*)&Bs[ch * RB + 2 * pp]        = hiw;
        *(uint32_t*)&Bs[(64 + ch) * RB + 2 * pp] = low;
    }
    __syncthreads();

    const int lane = tid & 31;
    const int wrp = tid >> 5;
    const int n0 = wrp << 4;               // 16 px per warp

    float acc[4][2][4];
#pragma unroll
    for (int mi = 0; mi < 4; mi++)
#pragma unroll
        for (int ni = 0; ni < 2; ni++)
#pragma unroll
            for (int j = 0; j < 4; j++) acc[mi][ni][j] = 0.f;

    const uint32_t As_u = smem_to_u32(As);
    const uint32_t Bs_u = smem_to_u32(Bs);
    const int arow = lane & 15;            // ldmatrix source row select
    const int acol8 = (lane >> 4) << 3;

#pragma unroll
    for (int s = 0; s < 12; s++) {
        const int akcol = (s < 8) ? ((s & 3) << 4) : (64 + ((s - 8) << 4));
        const int bkrow = (s < 4) ? (s << 4)
                        : ((s < 8) ? (64 + ((s - 4) << 4)) : ((s - 8) << 4));
        uint32_t a[4][4];
#pragma unroll
        for (int mi = 0; mi < 4; mi++) {
            uint32_t addr = As_u +
                (((mi << 4) + arow) * RA + akcol + acol8) * 2;
            asm volatile(
                "ldmatrix.sync.aligned.m8n8.x4.shared.b16 {%0,%1,%2,%3}, [%4];"
                : "=r"(a[mi][0]), "=r"(a[mi][1]), "=r"(a[mi][2]), "=r"(a[mi][3])
                : "r"(addr));
        }
        uint32_t bf[2][2];
#pragma unroll
        for (int ni = 0; ni < 2; ni++) {
            uint32_t addr = Bs_u +
                ((bkrow + arow) * RB + n0 + (ni << 3)) * 2;
            asm volatile(
                "ldmatrix.sync.aligned.m8n8.x2.trans.shared.b16 {%0,%1}, [%2];"
                : "=r"(bf[ni][0]), "=r"(bf[ni][1])
                : "r"(addr));
        }
#pragma unroll
        for (int mi = 0; mi < 4; mi++)
#pragma unroll
            for (int ni = 0; ni < 2; ni++) {
                asm volatile(
                    "mma.sync.aligned.m16n8k16.row.col.f32.bf16.bf16.f32 "
                    "{%0,%1,%2,%3}, {%4,%5,%6,%7}, {%8,%9}, {%0,%1,%2,%3};"
                    : "+f"(acc[mi][ni][0]), "+f"(acc[mi][ni][1]),
                      "+f"(acc[mi][ni][2]), "+f"(acc[mi][ni][3])
                    : "r"(a[mi][0]), "r"(a[mi][1]), "r"(a[mi][2]), "r"(a[mi][3]),
                      "r"(bf[ni][0]), "r"(bf[ni][1]));
            }
    }

    // ---- epilogue: c0,c1 = (oc, px), (oc, px+1); c2,c3 = oc+8 ----
    float* outp = dst + ((long)(b << 6) << 12) + hw0;
    const int ocb = lane >> 2;
    const int pxb = (lane & 3) << 1;
#pragma unroll
    for (int mi = 0; mi < 4; mi++)
#pragma unroll
        for (int ni = 0; ni < 2; ni++) {
            int oc = (mi << 4) + ocb;
            int px = n0 + (ni << 3) + pxb;
            *(float2*)(outp + oc * 4096 + px) =
                make_float2(acc[mi][ni][0], acc[mi][ni][1]);
            *(float2*)(outp + (oc + 8) * 4096 + px) =
                make_float2(acc[mi][ni][2], acc[mi][ni][3]);
        }
}

// ---------------------------------------------------------------------------
// Kernel 2: windowed per-channel softmax-attention (unchanged from R3).
// ---------------------------------------------------------------------------
#define KSW 76

__device__ __forceinline__ float ex2f(float v) {
    float r;
    asm("ex2.approx.ftz.f32 %0, %1;" : "=f"(r) : "f"(v));
    return r;
}

__global__ __launch_bounds__(128, 7) void attn_kernel(
    const float* __restrict__ rel_h, const float* __restrict__ rel_w,
    float* __restrict__ out) {
    __shared__ __align__(16) float ks[22 * KSW];
    __shared__ __align__(16) float vs[22 * KSW];

    const int tid = threadIdx.x;
    const int h0 = blockIdx.x << 4;
    const int c  = blockIdx.y;
    const int b  = blockIdx.z;
    const int plane = ((b << 6) + c) << 12;

    const float* bp = (c < 32) ? (rel_h + c * 7) : (rel_w + (c - 32) * 7);
    float bias7[7];
#pragma unroll
    for (int j = 0; j < 7; j++) bias7[j] = __ldg(bp + j);

    float4 z4 = make_float4(0.f, 0.f, 0.f, 0.f);
    for (int i = tid; i < (22 * KSW) / 4; i += 128) {
        ((float4*)ks)[i] = z4;
        ((float4*)vs)[i] = z4;
    }
    __syncthreads();

    const float* kp = g_k + plane;
    const float* vp = g_v + plane;
    for (int i = tid; i < 22 * 16; i += 128) {
        int r = i >> 4, c4 = (i & 15) << 2;
        int gr = h0 - 3 + r;
        if ((unsigned)gr < 64u) {
            float4 kv = *(const float4*)(kp + (gr << 6) + c4);
            float4 vv = *(const float4*)(vp + (gr << 6) + c4);
            int s0 = r * KSW + 3 + c4;
            ks[s0] = kv.x; ks[s0 + 1] = kv.y; ks[s0 + 2] = kv.z; ks[s0 + 3] = kv.w;
            vs[s0] = vv.x; vs[s0 + 1] = vv.y; vs[s0 + 2] = vv.z; vs[s0 + 3] = vv.w;
        }
    }
    __syncthreads();

    const int ty = tid >> 4;
    const int w0 = (tid & 15) << 2;
    const int r0 = h0 + (ty << 1);

    const float4 qa = *(const float4*)(g_q + plane + (r0 << 6) + w0);
    const float4 qb = *(const float4*)(g_q + plane + ((r0 + 1) << 6) + w0);
    float q2[8] = {qa.x * LOG2E, qa.y * LOG2E, qa.z * LOG2E, qa.w * LOG2E,
                   qb.x * LOG2E, qb.y * LOG2E, qb.z * LOG2E, qb.w * LOG2E};
    float s[8], a[8];
#pragma unroll
    for (int i = 0; i < 8; i++) { s[i] = 0.f; a[i] = 0.f; }

    if (c < 32) {
#pragma unroll
        for (int j = 0; j < 8; j++) {
            const float* krow = &ks[((ty << 1) + j) * KSW + w0];
            const float* vrow = &vs[((ty << 1) + j) * KSW + w0];
            float kr[12], vr[12];
            *(float4*)(kr)     = *(const float4*)(krow);
            *(float4*)(kr + 4) = *(const float4*)(krow + 4);
            *(float4*)(kr + 8) = *(const float4*)(krow + 8);
            *(float4*)(vr)     = *(const float4*)(vrow);
            *(float4*)(vr + 4) = *(const float4*)(vrow + 4);
            *(float4*)(vr + 8) = *(const float4*)(vrow + 8);
            if (j < 7) {
                float qb0[4];
#pragma unroll
                for (int i = 0; i < 4; i++) qb0[i] = q2[i] * bias7[j];
#pragma unroll
                for (int kw = 0; kw < 7; kw++)
#pragma unroll
                    for (int i = 0; i < 4; i++) {
                        float e = ex2f(fmaf(q2[i], kr[i + kw], qb0[i]));
                        s[i] += e;
                        a[i] = fmaf(e, vr[i + kw], a[i]);
                    }
            }
            if (j >= 1) {
                float qb1[4];
#pragma unroll
                for (int i = 0; i < 4; i++) qb1[i] = q2[4 + i] * bias7[j - 1];
#pragma unroll
                for (int kw = 0; kw < 7; kw++)
#pragma unroll
                    for (int i = 0; i < 4; i++) {
                        float e = ex2f(fmaf(q2[4 + i], kr[i + kw], qb1[i]));
                        s[4 + i] += e;
                        a[4 + i] = fmaf(e, vr[i + kw], a[4 + i]);
                    }
            }
        }
    } else {
#pragma unroll
        for (int j = 0; j < 8; j++) {
            const float* krow = &ks[((ty << 1) + j) * KSW + w0];
            const float* vrow = &vs[((ty << 1) + j) * KSW + w0];
            float kr[12], vr[12];
            *(float4*)(kr)     = *(const float4*)(krow);
            *(float4*)(kr + 4) = *(const float4*)(krow + 4);
            *(float4*)(kr + 8) = *(const float4*)(krow + 8);
            *(float4*)(vr)     = *(const float4*)(vrow);
            *(float4*)(vr + 4) = *(const float4*)(vrow + 4);
            *(float4*)(vr + 8) = *(const float4*)(vrow + 8);
            if (j < 7) {
#pragma unroll
                for (int kw = 0; kw < 7; kw++) {
                    float bb = bias7[kw];
#pragma unroll
                    for (int i = 0; i < 4; i++) {
                        float e = ex2f(q2[i] * (kr[i + kw] + bb));
                        s[i] += e;
                        a[i] = fmaf(e, vr[i + kw], a[i]);
                    }
                }
            }
            if (j >= 1) {
#pragma unroll
                for (int kw = 0; kw < 7; kw++) {
                    float bb = bias7[kw];
#pragma unroll
                    for (int i = 0; i < 4; i++) {
                        float e = ex2f(q2[4 + i] * (kr[i + kw] + bb));
                        s[4 + i] += e;
                        a[4 + i] = fmaf(e, vr[i + kw], a[4 + i]);
                    }
                }
            }
        }
    }

    float4 o0, o1;
    o0.x = __fdividef(a[0], s[0]);
    o0.y = __fdividef(a[1], s[1]);
    o0.z = __fdividef(a[2], s[2]);
    o0.w = __fdividef(a[3], s[3]);
    o1.x = __fdividef(a[4], s[4]);
    o1.y = __fdividef(a[5], s[5]);
    o1.z = __fdividef(a[6], s[6]);
    o1.w = __fdividef(a[7], s[7]);
    *(float4*)(out + plane + (r0 << 6) + w0) = o0;
    *(float4*)(out + plane + ((r0 + 1) << 6) + w0) = o1;
}

extern "C" void kernel_launch(void* const* d_in, const int* in_sizes, int n_in,
                              void* d_out, int out_size) {
    const float* x     = (const float*)d_in[0];
    const float* y     = (const float*)d_in[1];
    const float* Wq    = (const float*)d_in[2];
    const float* Wk    = (const float*)d_in[3];
    const float* Wv    = (const float*)d_in[4];
    const float* rel_h = (const float*)d_in[5];
    const float* rel_w = (const float*)d_in[6];
    float* out = (float*)d_out;

    dim3 g1(256, 3, 1);
    qkv_mma_kernel<<<g1, 128>>>(x, y, Wq, Wk, Wv);

    dim3 g2(4, 64, 4);
    attn_kernel<<<g2, 128>>>(rel_h, rel_w, out);
}

// round 8
// speedup vs baseline: 1.2760x; 1.2760x over previous
#include <cuda_runtime.h>

// AttentionConv: q,k,v = 1x1 convs; per-channel softmax over 7x7 window of
// q*(k+bias); out = sum attn*v.  B=4, C=Cout=64, H=W=64, K=7, PAD=3.
//
// R7 == R6 resubmitted (R6 bench was an infra failure, no signal).
// R6: qkv reverted to the proven R3 FFMA GEMM (fma-pipe floor ~11.4us;
//     tcgen05 is toolchain-gated and warp mma.sync bf16 measured SLOWER).
//     attn: prologue software-pipelined -- all LDG issued before the smem
//     zero-fill so memory latency hides under STS; loads consumed post-sync.

#define LOG2E 1.4426950408889634f

__device__ float g_q[4 * 64 * 64 * 64];
__device__ float g_k[4 * 64 * 64 * 64];
__device__ float g_v[4 * 64 * 64 * 64];

__device__ __forceinline__ float ex2f(float v) {
    float r;
    asm("ex2.approx.ftz.f32 %0, %1;" : "=f"(r) : "f"(v));
    return r;
}

__device__ __forceinline__ unsigned long long fma_f32x2(
    unsigned long long a, unsigned long long b, unsigned long long c) {
    unsigned long long d;
    asm("fma.rn.f32x2 %0, %1, %2, %3;" : "=l"(d) : "l"(a), "l"(b), "l"(c));
    return d;
}

__device__ __forceinline__ unsigned long long dupf(float v) {
    unsigned long long r;
    asm("mov.b64 %0, {%1, %1};" : "=l"(r) : "f"(v));
    return r;
}

// ---------------------------------------------------------------------------
// Kernel 1: qkv projections (R3 version, unchanged).  128 threads,
// 64o x 64px tile, 768 blocks.  ws[c][o] = W^T stride 66 (coalesced LDG +
// 2-way STS scatter); xs[c][p].  Thread tile 8o x 4px as 4 o-pairs.
// ---------------------------------------------------------------------------
#define WSTR 66

__global__ __launch_bounds__(128) void qkv_kernel(
    const float* __restrict__ x, const float* __restrict__ y,
    const float* __restrict__ Wq, const float* __restrict__ Wk,
    const float* __restrict__ Wv) {
    __shared__ __align__(16) float ws[64 * WSTR];
    __shared__ __align__(16) float xs[64 * 64];

    const int mat = blockIdx.y;
    const float* Wsrc = (mat == 0) ? Wq : ((mat == 1) ? Wk : Wv);
    const float* src  = (mat == 2) ? y : x;
    float* dst = (mat == 0) ? g_q : ((mat == 1) ? g_k : g_v);

    const int tid = threadIdx.x;
    const int pix0 = blockIdx.x * 64;
    const int b = pix0 >> 12;
    const int hw0 = pix0 & 4095;

#pragma unroll
    for (int i = 0; i < 32; i++) {
        int idx = tid + i * 128;           // = o*64 + c
        ws[(idx & 63) * WSTR + (idx >> 6)] = Wsrc[idx];
    }
#pragma unroll
    for (int i = 0; i < 32; i++) {
        int idx = tid + i * 128;           // = c*64 + p
        xs[idx] = src[((b << 6) + (idx >> 6)) * 4096 + hw0 + (idx & 63)];
    }
    __syncthreads();

    const int o0 = (tid >> 4) << 3;
    const int p0 = (tid & 15) << 2;

    unsigned long long acc[4][4];
#pragma unroll
    for (int i = 0; i < 4; i++)
#pragma unroll
        for (int j = 0; j < 4; j++) acc[i][j] = 0ULL;

#pragma unroll 4
    for (int cc = 0; cc < 64; cc++) {
        float4 xv = *(const float4*)(xs + (cc << 6) + p0);
        unsigned long long dx0 = dupf(xv.x);
        unsigned long long dx1 = dupf(xv.y);
        unsigned long long dx2 = dupf(xv.z);
        unsigned long long dx3 = dupf(xv.w);
        const float* wrow = ws + cc * WSTR + o0;
        unsigned long long wp0 = *(const unsigned long long*)(wrow);
        unsigned long long wp1 = *(const unsigned long long*)(wrow + 2);
        unsigned long long wp2 = *(const unsigned long long*)(wrow + 4);
        unsigned long long wp3 = *(const unsigned long long*)(wrow + 6);
        acc[0][0] = fma_f32x2(wp0, dx0, acc[0][0]);
        acc[0][1] = fma_f32x2(wp0, dx1, acc[0][1]);
        acc[0][2] = fma_f32x2(wp0, dx2, acc[0][2]);
        acc[0][3] = fma_f32x2(wp0, dx3, acc[0][3]);
        acc[1][0] = fma_f32x2(wp1, dx0, acc[1][0]);
        acc[1][1] = fma_f32x2(wp1, dx1, acc[1][1]);
        acc[1][2] = fma_f32x2(wp1, dx2, acc[1][2]);
        acc[1][3] = fma_f32x2(wp1, dx3, acc[1][3]);
        acc[2][0] = fma_f32x2(wp2, dx0, acc[2][0]);
        acc[2][1] = fma_f32x2(wp2, dx1, acc[2][1]);
        acc[2][2] = fma_f32x2(wp2, dx2, acc[2][2]);
        acc[2][3] = fma_f32x2(wp2, dx3, acc[2][3]);
        acc[3][0] = fma_f32x2(wp3, dx0, acc[3][0]);
        acc[3][1] = fma_f32x2(wp3, dx1, acc[3][1]);
        acc[3][2] = fma_f32x2(wp3, dx2, acc[3][2]);
        acc[3][3] = fma_f32x2(wp3, dx3, acc[3][3]);
    }

#pragma unroll
    for (int o2 = 0; o2 < 4; o2++) {
        float2 v0 = *reinterpret_cast<float2*>(&acc[o2][0]);
        float2 v1 = *reinterpret_cast<float2*>(&acc[o2][1]);
        float2 v2 = *reinterpret_cast<float2*>(&acc[o2][2]);
        float2 v3 = *reinterpret_cast<float2*>(&acc[o2][3]);
        float* base = dst + ((b << 6) + o0 + 2 * o2) * 4096 + hw0 + p0;
        *(float4*)(base)        = make_float4(v0.x, v1.x, v2.x, v3.x);
        *(float4*)(base + 4096) = make_float4(v0.y, v1.y, v2.y, v3.y);
    }
}

// ---------------------------------------------------------------------------
// Kernel 2: windowed per-channel softmax-attention.
// R6 change: all global loads (q + 3 predicated k/v float4-pairs/thread)
// issued BEFORE the zero-fill; stored to smem after the barrier.
// ---------------------------------------------------------------------------
#define KSW 76

__global__ __launch_bounds__(128, 7) void attn_kernel(
    const float* __restrict__ rel_h, const float* __restrict__ rel_w,
    float* __restrict__ out) {
    __shared__ __align__(16) float ks[22 * KSW];
    __shared__ __align__(16) float vs[22 * KSW];

    const int tid = threadIdx.x;
    const int h0 = blockIdx.x << 4;
    const int c  = blockIdx.y;
    const int b  = blockIdx.z;
    const int plane = ((b << 6) + c) << 12;

    const int ty = tid >> 4;
    const int w0 = (tid & 15) << 2;
    const int r0 = h0 + (ty << 1);

    // ---- issue ALL global loads up front ----
    const float* kp = g_k + plane;
    const float* vp = g_v + plane;
    float4 kreg[3], vreg[3];
    bool inb[3];
    int soff[3];
#pragma unroll
    for (int it = 0; it < 3; it++) {
        int i = tid + it * 128;            // 0..351 (22 rows x 16 col-groups)
        int r = i >> 4, c4 = (i & 15) << 2;
        int gr = h0 - 3 + r;
        bool valid = (i < 352) && ((unsigned)gr < 64u);
        inb[it] = valid;
        soff[it] = r * KSW + 3 + c4;
        if (valid) {
            kreg[it] = *(const float4*)(kp + (gr << 6) + c4);
            vreg[it] = *(const float4*)(vp + (gr << 6) + c4);
        }
    }
    const float4 qa = *(const float4*)(g_q + plane + (r0 << 6) + w0);
    const float4 qb = *(const float4*)(g_q + plane + ((r0 + 1) << 6) + w0);

    const float* bp = (c < 32) ? (rel_h + c * 7) : (rel_w + (c - 32) * 7);
    float bias7[7];
#pragma unroll
    for (int j = 0; j < 7; j++) bias7[j] = __ldg(bp + j);

    // ---- zero-fill while loads are in flight ----
    float4 z4 = make_float4(0.f, 0.f, 0.f, 0.f);
    for (int i = tid; i < (22 * KSW) / 4; i += 128) {
        ((float4*)ks)[i] = z4;
        ((float4*)vs)[i] = z4;
    }
    __syncthreads();

    // ---- commit interior values ----
#pragma unroll
    for (int it = 0; it < 3; it++) {
        if (inb[it]) {
            int s0 = soff[it];
            ks[s0] = kreg[it].x; ks[s0 + 1] = kreg[it].y;
            ks[s0 + 2] = kreg[it].z; ks[s0 + 3] = kreg[it].w;
            vs[s0] = vreg[it].x; vs[s0 + 1] = vreg[it].y;
            vs[s0 + 2] = vreg[it].z; vs[s0 + 3] = vreg[it].w;
        }
    }
    __syncthreads();

    float q2[8] = {qa.x * LOG2E, qa.y * LOG2E, qa.z * LOG2E, qa.w * LOG2E,
                   qb.x * LOG2E, qb.y * LOG2E, qb.z * LOG2E, qb.w * LOG2E};
    float s[8], a[8];
#pragma unroll
    for (int i = 0; i < 8; i++) { s[i] = 0.f; a[i] = 0.f; }

    if (c < 32) {
#pragma unroll
        for (int j = 0; j < 8; j++) {
            const float* krow = &ks[((ty << 1) + j) * KSW + w0];
            const float* vrow = &vs[((ty << 1) + j) * KSW + w0];
            float kr[12], vr[12];
            *(float4*)(kr)     = *(const float4*)(krow);
            *(float4*)(kr + 4) = *(const float4*)(krow + 4);
            *(float4*)(kr + 8) = *(const float4*)(krow + 8);
            *(float4*)(vr)     = *(const float4*)(vrow);
            *(float4*)(vr + 4) = *(const float4*)(vrow + 4);
            *(float4*)(vr + 8) = *(const float4*)(vrow + 8);
            if (j < 7) {
                float qb0[4];
#pragma unroll
                for (int i = 0; i < 4; i++) qb0[i] = q2[i] * bias7[j];
#pragma unroll
                for (int kw = 0; kw < 7; kw++)
#pragma unroll
                    for (int i = 0; i < 4; i++) {
                        float e = ex2f(fmaf(q2[i], kr[i + kw], qb0[i]));
                        s[i] += e;
                        a[i] = fmaf(e, vr[i + kw], a[i]);
                    }
            }
            if (j >= 1) {
                float qb1[4];
#pragma unroll
                for (int i = 0; i < 4; i++) qb1[i] = q2[4 + i] * bias7[j - 1];
#pragma unroll
                for (int kw = 0; kw < 7; kw++)
#pragma unroll
                    for (int i = 0; i < 4; i++) {
                        float e = ex2f(fmaf(q2[4 + i], kr[i + kw], qb1[i]));
                        s[4 + i] += e;
                        a[4 + i] = fmaf(e, vr[i + kw], a[4 + i]);
                    }
            }
        }
    } else {
#pragma unroll
        for (int j = 0; j < 8; j++) {
            const float* krow = &ks[((ty << 1) + j) * KSW + w0];
            const float* vrow = &vs[((ty << 1) + j) * KSW + w0];
            float kr[12], vr[12];
            *(float4*)(kr)     = *(const float4*)(krow);
            *(float4*)(kr + 4) = *(const float4*)(krow + 4);
            *(float4*)(kr + 8) = *(const float4*)(krow + 8);
            *(float4*)(vr)     = *(const float4*)(vrow);
            *(float4*)(vr + 4) = *(const float4*)(vrow + 4);
            *(float4*)(vr + 8) = *(const float4*)(vrow + 8);
            if (j < 7) {
#pragma unroll
                for (int kw = 0; kw < 7; kw++) {
                    float bb = bias7[kw];
#pragma unroll
                    for (int i = 0; i < 4; i++) {
                        float e = ex2f(q2[i] * (kr[i + kw] + bb));
                        s[i] += e;
                        a[i] = fmaf(e, vr[i + kw], a[i]);
                    }
                }
            }
            if (j >= 1) {
#pragma unroll
                for (int kw = 0; kw < 7; kw++) {
                    float bb = bias7[kw];
#pragma unroll
                    for (int i = 0; i < 4; i++) {
                        float e = ex2f(q2[4 + i] * (kr[i + kw] + bb));
                        s[4 + i] += e;
                        a[4 + i] = fmaf(e, vr[i + kw], a[4 + i]);
                    }
                }
            }
        }
    }

    float4 o0, o1;
    o0.x = __fdividef(a[0], s[0]);
    o0.y = __fdividef(a[1], s[1]);
    o0.z = __fdividef(a[2], s[2]);
    o0.w = __fdividef(a[3], s[3]);
    o1.x = __fdividef(a[4], s[4]);
    o1.y = __fdividef(a[5], s[5]);
    o1.z = __fdividef(a[6], s[6]);
    o1.w = __fdividef(a[7], s[7]);
    *(float4*)(out + plane + (r0 << 6) + w0) = o0;
    *(float4*)(out + plane + ((r0 + 1) << 6) + w0) = o1;
}

extern "C" void kernel_launch(void* const* d_in, const int* in_sizes, int n_in,
                              void* d_out, int out_size) {
    const float* x     = (const float*)d_in[0];
    const float* y     = (const float*)d_in[1];
    const float* Wq    = (const float*)d_in[2];
    const float* Wk    = (const float*)d_in[3];
    const float* Wv    = (const float*)d_in[4];
    const float* rel_h = (const float*)d_in[5];
    const float* rel_w = (const float*)d_in[6];
    float* out = (float*)d_out;

    dim3 g1(256, 3, 1);
    qkv_kernel<<<g1, 128>>>(x, y, Wq, Wk, Wv);

    dim3 g2(4, 64, 4);
    attn_kernel<<<g2, 128>>>(rel_h, rel_w, out);
}